// round 13
// baseline (speedup 1.0000x reference)
#include <cuda_runtime.h>
#include <cuda_fp16.h>
#include <math.h>
#include <stdint.h>

#define Bq   16
#define Sq   256
#define NV   196
#define Dm   768
#define FFd  2048
#define VOC  30522
#define NL   6
#define NHh  8
#define HD   96
#define NTOK (Bq*Sq)        // 4096
#define NMEM (Bq*NV)        // 3136
#define NDEC (Bq*(Sq-1))    // 4080

// -------- scratch (device globals; no allocations allowed) --------
__device__ float  g_x   [NTOK*Dm];
__device__ float  g_o   [NTOK*Dm];
__device__ float  g_q   [NTOK*Dm];
__device__ float  g_qkv [NTOK*3*Dm];
__device__ float  g_kv  [NMEM*2*Dm];
__device__ float  g_dec [NDEC*Dm];
// fp16 activations
__device__ __half g_hx   [NTOK*Dm];
__device__ __half g_hattn[NTOK*Dm];
__device__ __half g_hff  [NTOK*FFd];
__device__ __half g_hdec [NDEC*Dm];
__device__ __half g_hfv  [NMEM*Dm];
// fp16 weights (converted once per launch)
__device__ __half g_h_si[NL*3*Dm*Dm];
__device__ __half g_h_so[NL*Dm*Dm];
__device__ __half g_h_ci[NL*3*Dm*Dm];
__device__ __half g_h_co[NL*Dm*Dm];
__device__ __half g_h_l1[NL*FFd*Dm];
__device__ __half g_h_l2[NL*Dm*FFd];
__device__ __half g_h_fc[(long)VOC*Dm];

// -------- fp32 -> fp16 bulk convert (8 elems/thread) --------
__global__ void f2h_kernel(const float* __restrict__ in, __half* __restrict__ out, int n)
{
    int i = (blockIdx.x * 256 + threadIdx.x) * 8;
    if (i >= n) return;
    float4 v0 = *(const float4*)&in[i];
    float4 v1 = *(const float4*)&in[i + 4];
    uint2 o0, o1;
    __half2 h;
    h = __floats2half2_rn(v0.x, v0.y); o0.x = *(uint32_t*)&h;
    h = __floats2half2_rn(v0.z, v0.w); o0.y = *(uint32_t*)&h;
    h = __floats2half2_rn(v1.x, v1.y); o1.x = *(uint32_t*)&h;
    h = __floats2half2_rn(v1.z, v1.w); o1.y = *(uint32_t*)&h;
    *(uint2*)&out[i]     = o0;
    *(uint2*)&out[i + 4] = o1;
}

// ================== FP16 GEMM: 3-stage ring, 1 sync/tile ================
// C[M,N] = A[M,K] @ W[N,K]^T (+bias)(+relu), fp32 accumulate.
// A, W fp16. Output fp32 (Cf) or fp16 (Ch) — exactly one non-null.
#define BM 128
#define BN 128
#define BK 16
#define PADW 12
#define NSTG 3

__device__ __forceinline__ uint32_t cvta_smem(const void* p) {
    uint32_t a;
    asm("{ .reg .u64 t; cvta.to.shared.u64 t, %1; cvt.u32.u64 %0, t; }"
        : "=r"(a) : "l"(p));
    return a;
}

__device__ __forceinline__ void mma_f16(
    float& c0, float& c1, float& c2, float& c3,
    uint32_t a0, uint32_t a1, uint32_t a2, uint32_t a3,
    uint32_t b0, uint32_t b1)
{
    asm volatile(
        "mma.sync.aligned.m16n8k16.row.col.f32.f16.f16.f32 "
        "{%0,%1,%2,%3}, {%4,%5,%6,%7}, {%8,%9}, {%0,%1,%2,%3};"
        : "+f"(c0), "+f"(c1), "+f"(c2), "+f"(c3)
        : "r"(a0), "r"(a1), "r"(a2), "r"(a3), "r"(b0), "r"(b1));
}

#define LDM_X4(r, addr) \
    asm volatile("ldmatrix.sync.aligned.m8n8.x4.shared.b16 {%0,%1,%2,%3}, [%4];" \
        : "=r"((r)[0]), "=r"((r)[1]), "=r"((r)[2]), "=r"((r)[3]) : "r"(addr))

__global__ __launch_bounds__(256, 2) void mma_gemm(
    const __half* __restrict__ A, const __half* __restrict__ W,
    const float* __restrict__ bias,
    float* __restrict__ Cf, __half* __restrict__ Ch,
    int M, int N, int K, int relu)
{
    __shared__ uint32_t As[NSTG][BM * PADW];
    __shared__ uint32_t Bs[NSTG][BN * PADW];

    int tid  = threadIdx.x;
    int wid  = tid >> 5, lane = tid & 31;
    int g    = lane >> 2;
    int t4   = lane & 3;
    int wm   = (wid >> 2) * 64;
    int wn   = (wid & 3) * 32;
    int m0   = blockIdx.y * BM, n0 = blockIdx.x * BN;

    // global-load mapping: tile = 128 rows x 16 halves (32B); 2 threads/row
    int r = tid >> 1, c = tid & 1;
    int ra = m0 + r; if (ra > M - 1) ra = M - 1;
    int rb = n0 + r; if (rb > N - 1) rb = N - 1;
    const __half* Ap = A + (long)ra * K + c * 8;
    const __half* Wp = W + (long)rb * K + c * 8;
    int sidx = r * PADW + c * 4;

    // ldmatrix per-lane source offsets (bytes)
    int rA  = lane & 15, khA = lane >> 4;
    uint32_t aoff = (uint32_t)(((wm + rA) * PADW + khA * 4) * 4);
    int qd = lane >> 3, rB = lane & 7;
    uint32_t boff = (uint32_t)(((wn + ((qd >> 1) * 8) + rB) * PADW + (qd & 1) * 4) * 4);

    uint32_t asb[NSTG], bsb[NSTG];
    #pragma unroll
    for (int s = 0; s < NSTG; s++) {
        asb[s] = cvta_smem(As[s]);
        bsb[s] = cvta_smem(Bs[s]);
    }

    float acc[4][4][4];
    #pragma unroll
    for (int i = 0; i < 4; i++)
        #pragma unroll
        for (int j = 0; j < 4; j++)
            #pragma unroll
            for (int k = 0; k < 4; k++) acc[i][j][k] = 0.f;

    int nk = K / BK;
    // prologue: tile0 -> smem[0]; tile1 regs in flight
    uint4 cu_a = *(const uint4*)(Ap);
    uint4 cu_b = *(const uint4*)(Wp);
    *(uint4*)&As[0][sidx] = cu_a;
    *(uint4*)&Bs[0][sidx] = cu_b;
    if (nk > 1) {
        cu_a = *(const uint4*)(Ap + BK);
        cu_b = *(const uint4*)(Wp + BK);
    }

    for (int t = 0; t < nk; t++) {
        // store tile t+1 (regs loaded at iter t-1), then prefetch tile t+2
        if (t + 1 < nk) {
            int s = (t + 1) % NSTG;
            *(uint4*)&As[s][sidx] = cu_a;
            *(uint4*)&Bs[s][sidx] = cu_b;
            if (t + 2 < nk) {
                cu_a = *(const uint4*)(Ap + (t + 2) * BK);
                cu_b = *(const uint4*)(Wp + (t + 2) * BK);
            }
        }
        __syncthreads();

        int buf = t % NSTG;
        uint32_t af[4][4], bf[4][2];
        #pragma unroll
        for (int mt = 0; mt < 4; mt++)
            LDM_X4(af[mt], asb[buf] + aoff + (uint32_t)(mt * 16 * PADW * 4));
        #pragma unroll
        for (int p = 0; p < 2; p++) {
            uint32_t bb[4];
            LDM_X4(bb, bsb[buf] + boff + (uint32_t)(p * 16 * PADW * 4));
            bf[2*p][0]   = bb[0]; bf[2*p][1]   = bb[1];
            bf[2*p+1][0] = bb[2]; bf[2*p+1][1] = bb[3];
        }
        #pragma unroll
        for (int mt = 0; mt < 4; mt++)
            #pragma unroll
            for (int nt = 0; nt < 4; nt++)
                mma_f16(acc[mt][nt][0], acc[mt][nt][1], acc[mt][nt][2], acc[mt][nt][3],
                        af[mt][0], af[mt][1], af[mt][2], af[mt][3],
                        bf[nt][0], bf[nt][1]);
    }

    // epilogue
    #pragma unroll
    for (int mt = 0; mt < 4; mt++) {
        int row = m0 + wm + mt * 16 + g;
        #pragma unroll
        for (int nt = 0; nt < 4; nt++) {
            int col = n0 + wn + nt * 8 + t4 * 2;
            float v0 = acc[mt][nt][0], v1 = acc[mt][nt][1];
            float v2 = acc[mt][nt][2], v3 = acc[mt][nt][3];
            if (bias) {
                float b0 = (col < N) ? bias[col] : 0.f;
                float b1 = (col + 1 < N) ? bias[col + 1] : 0.f;
                v0 += b0; v1 += b1; v2 += b0; v3 += b1;
            }
            if (relu) {
                v0 = fmaxf(v0, 0.f); v1 = fmaxf(v1, 0.f);
                v2 = fmaxf(v2, 0.f); v3 = fmaxf(v3, 0.f);
            }
            if (Ch) {
                if (row < M && col + 1 < N)
                    *(__half2*)&Ch[(long)row * N + col] = __floats2half2_rn(v0, v1);
                if (row + 8 < M && col + 1 < N)
                    *(__half2*)&Ch[(long)(row + 8) * N + col] = __floats2half2_rn(v2, v3);
            } else {
                if (row < M) {
                    if (col + 1 < N) *(float2*)&Cf[(long)row * N + col] = make_float2(v0, v1);
                    else if (col < N) Cf[(long)row * N + col] = v0;
                }
                if (row + 8 < M) {
                    if (col + 1 < N) *(float2*)&Cf[(long)(row + 8) * N + col] = make_float2(v2, v3);
                    else if (col < N) Cf[(long)(row + 8) * N + col] = v2;
                }
            }
        }
    }
}

// ================== tiled smem attention (fp32 in, fp16 out) =============
// Qs/Ks stride 100 floats: 16B-aligned rows; for LDS.128 each 8-lane phase
// covers all 32 banks (lane*100 mod 32 = 4*lane), conflict-free.
#define TQ 16
#define KCH 32
#define QKP 100

__global__ __launch_bounds__(128) void attn_tile(
    const float* __restrict__ Q, int qs,
    const float* __restrict__ Kt, int ks,
    const float* __restrict__ Vt, int vs,
    __half* __restrict__ O, int os,
    int Lk, int causal)
{
    __shared__ __align__(16) float Qs[TQ][QKP];
    __shared__ __align__(16) float Ks[KCH][QKP];
    __shared__ __align__(16) float Vs[KCH][HD];
    __shared__ float Sc[TQ][Sq];
    __shared__ float invr[TQ];

    int tid  = threadIdx.x;
    int warp = tid >> 5, lane = tid & 31;
    int q0   = blockIdx.x * TQ;
    int h    = blockIdx.y, b = blockIdx.z;

    const float* Qb = Q  + ((long)b * Sq + q0) * qs + h * HD;
    const float* Kb = Kt + (long)b * Lk * ks + h * HD;
    const float* Vb = Vt + (long)b * Lk * vs + h * HD;

    for (int i = tid; i < TQ * HD; i += 128) {
        int rr = i / HD, cc = i % HD;
        Qs[rr][cc] = Qb[(long)rr * qs + cc];
    }

    const float scale = rsqrtf((float)HD);
    int nch = (Lk + KCH - 1) / KCH;

    for (int kc = 0; kc < nch; kc++) {
        int k0 = kc * KCH;
        __syncthreads();
        for (int i = tid; i < KCH * HD; i += 128) {
            int rr = i / HD, cc = i % HD;
            Ks[rr][cc] = (k0 + rr < Lk) ? Kb[(long)(k0 + rr) * ks + cc] : 0.f;
        }
        __syncthreads();
        int j = k0 + lane;
        float s0 = 0.f, s1 = 0.f, s2 = 0.f, s3 = 0.f;
        const float* krow = Ks[lane];
        const float* q0p = Qs[warp * 4 + 0];
        const float* q1p = Qs[warp * 4 + 1];
        const float* q2p = Qs[warp * 4 + 2];
        const float* q3p = Qs[warp * 4 + 3];
        #pragma unroll
        for (int t = 0; t < HD; t += 4) {
            float4 kv = *(const float4*)&krow[t];
            float4 a0 = *(const float4*)&q0p[t];
            float4 a1 = *(const float4*)&q1p[t];
            float4 a2 = *(const float4*)&q2p[t];
            float4 a3 = *(const float4*)&q3p[t];
            s0 += a0.x*kv.x + a0.y*kv.y + a0.z*kv.z + a0.w*kv.w;
            s1 += a1.x*kv.x + a1.y*kv.y + a1.z*kv.z + a1.w*kv.w;
            s2 += a2.x*kv.x + a2.y*kv.y + a2.z*kv.z + a2.w*kv.w;
            s3 += a3.x*kv.x + a3.y*kv.y + a3.z*kv.z + a3.w*kv.w;
        }
        #pragma unroll
        for (int qi = 0; qi < 4; qi++) {
            int q = warp * 4 + qi;
            float s = (qi == 0) ? s0 : (qi == 1) ? s1 : (qi == 2) ? s2 : s3;
            s *= scale;
            if (j >= Lk || (causal && j > q0 + q)) s = -1e30f;
            Sc[q][j] = s;
        }
    }
    __syncthreads();

    int nk32 = nch * KCH;
    #pragma unroll
    for (int qi = 0; qi < 4; qi++) {
        int q = warp * 4 + qi;
        float mx = -1e30f;
        for (int j = lane; j < nk32; j += 32) mx = fmaxf(mx, Sc[q][j]);
        #pragma unroll
        for (int o = 16; o; o >>= 1) mx = fmaxf(mx, __shfl_xor_sync(~0u, mx, o));
        float sum = 0.f;
        for (int j = lane; j < nk32; j += 32) {
            float e = __expf(Sc[q][j] - mx);
            Sc[q][j] = e;
            sum += e;
        }
        #pragma unroll
        for (int o = 16; o; o >>= 1) sum += __shfl_xor_sync(~0u, sum, o);
        if (lane == 0) invr[q] = 1.f / sum;
    }

    int qa = tid >> 3;
    int dbase = (tid & 7) * 12;
    float acc[12];
    #pragma unroll
    for (int i = 0; i < 12; i++) acc[i] = 0.f;

    for (int kc = 0; kc < nch; kc++) {
        int k0 = kc * KCH;
        __syncthreads();
        for (int i = tid; i < KCH * HD; i += 128) {
            int rr = i / HD, cc = i % HD;
            Vs[rr][cc] = (k0 + rr < Lk) ? Vb[(long)(k0 + rr) * vs + cc] : 0.f;
        }
        __syncthreads();
        #pragma unroll
        for (int j = 0; j < KCH; j++) {
            float p = Sc[qa][k0 + j];
            float4 v0 = *(const float4*)&Vs[j][dbase];
            float4 v1 = *(const float4*)&Vs[j][dbase + 4];
            float4 v2 = *(const float4*)&Vs[j][dbase + 8];
            acc[0] += p * v0.x; acc[1]  += p * v0.y; acc[2]  += p * v0.z; acc[3]  += p * v0.w;
            acc[4] += p * v1.x; acc[5]  += p * v1.y; acc[6]  += p * v1.z; acc[7]  += p * v1.w;
            acc[8] += p * v2.x; acc[9]  += p * v2.y; acc[10] += p * v2.z; acc[11] += p * v2.w;
        }
    }
    float inv = invr[qa];
    __half* op = O + ((long)b * Sq + q0 + qa) * os + h * HD + dbase;
    #pragma unroll
    for (int i = 0; i < 12; i += 2)
        *(__half2*)&op[i] = __floats2half2_rn(acc[i] * inv, acc[i + 1] * inv);
}

// -------- residual add + layernorm (in-place on X, dual write fp16) ------
__global__ __launch_bounds__(256) void add_ln_kernel(
    float* __restrict__ X, const float* __restrict__ Y,
    const float* __restrict__ w, const float* __restrict__ b,
    __half* __restrict__ HX)
{
    long t = blockIdx.x;
    int tid = threadIdx.x;
    __shared__ float red[256];
    float vals[3];
    float s = 0.f;
    #pragma unroll
    for (int i = 0; i < 3; i++) {
        int d = tid + i * 256;
        float v = X[t * Dm + d] + Y[t * Dm + d];
        vals[i] = v;
        s += v;
    }
    red[tid] = s; __syncthreads();
    for (int st = 128; st > 0; st >>= 1) {
        if (tid < st) red[tid] += red[tid + st];
        __syncthreads();
    }
    float mean = red[0] * (1.f / Dm);
    __syncthreads();
    float s2 = 0.f;
    #pragma unroll
    for (int i = 0; i < 3; i++) { float dv = vals[i] - mean; s2 += dv * dv; }
    red[tid] = s2; __syncthreads();
    for (int st = 128; st > 0; st >>= 1) {
        if (tid < st) red[tid] += red[tid + st];
        __syncthreads();
    }
    float rstd = rsqrtf(red[0] * (1.f / Dm) + 1e-5f);
    #pragma unroll
    for (int i = 0; i < 3; i++) {
        int d = tid + i * 256;
        float o = (vals[i] - mean) * rstd * w[d] + b[d];
        X[t * Dm + d]  = o;
        HX[t * Dm + d] = __float2half_rn(o);
    }
}

// -------- x = target_embed + sinusoid PE (dual write) --------
__global__ void pe_kernel(const float* __restrict__ te,
                          float* __restrict__ x, __half* __restrict__ hx)
{
    int idx = blockIdx.x * 256 + threadIdx.x;
    if (idx >= NTOK * Dm) return;
    int d = idx % Dm;
    int tok = idx / Dm;
    int s = tok % Sq;
    int j = d >> 1;
    float div = expf(-(float)(2 * j) * (logf(10000.f) / (float)Dm));
    float ang = (float)s * div;
    float p = (d & 1) ? cosf(ang) : sinf(ang);
    float o = te[idx] + p;
    x[idx]  = o;
    hx[idx] = __float2half_rn(o);
}

// -------- gather dec = x[:, :S-1, :] (dual write) --------
__global__ void dec_gather(const float* __restrict__ x,
                           float* __restrict__ dec, __half* __restrict__ hdec)
{
    int idx = blockIdx.x * 256 + threadIdx.x;
    if (idx >= NDEC * Dm) return;
    int d = idx % Dm;
    int rr = idx / Dm;
    int b = rr / (Sq - 1);
    int s = rr % (Sq - 1);
    float v = x[((long)(b * Sq + s)) * Dm + d];
    dec[idx]  = v;
    hdec[idx] = __float2half_rn(v);
}

// -------- F_t = softmax(dec, axis=-1) --------
__global__ __launch_bounds__(256) void ft_softmax(
    const float* __restrict__ dec, float* __restrict__ out)
{
    long rr = blockIdx.x;
    int tid = threadIdx.x;
    __shared__ float red[256];
    float v[3];
    float mx = -1e30f;
    #pragma unroll
    for (int i = 0; i < 3; i++) {
        v[i] = dec[rr * Dm + tid + i * 256];
        mx = fmaxf(mx, v[i]);
    }
    red[tid] = mx; __syncthreads();
    for (int st = 128; st > 0; st >>= 1) {
        if (tid < st) red[tid] = fmaxf(red[tid], red[tid + st]);
        __syncthreads();
    }
    float m = red[0]; __syncthreads();
    float s = 0.f;
    #pragma unroll
    for (int i = 0; i < 3; i++) { v[i] = __expf(v[i] - m); s += v[i]; }
    red[tid] = s; __syncthreads();
    for (int st = 128; st > 0; st >>= 1) {
        if (tid < st) red[tid] += red[tid + st];
        __syncthreads();
    }
    float inv = 1.f / red[0];
    #pragma unroll
    for (int i = 0; i < 3; i++)
        out[rr * Dm + tid + i * 256] = v[i] * inv;
}

static inline dim3 gemm_grid(int M, int N) {
    return dim3((N + BN - 1) / BN, (M + BM - 1) / BM);
}
static inline int conv_grid(long n) { return (int)((n / 8 + 255) / 256); }

extern "C" void kernel_launch(void* const* d_in, const int* in_sizes, int n_in,
                              void* d_out, int out_size)
{
    const float* fv          = (const float*)d_in[0];
    const float* te          = (const float*)d_in[1];
    const float* self_in_w   = (const float*)d_in[2];
    const float* self_in_b   = (const float*)d_in[3];
    const float* self_out_w  = (const float*)d_in[4];
    const float* self_out_b  = (const float*)d_in[5];
    const float* cross_in_w  = (const float*)d_in[6];
    const float* cross_in_b  = (const float*)d_in[7];
    const float* cross_out_w = (const float*)d_in[8];
    const float* cross_out_b = (const float*)d_in[9];
    const float* lin1_w      = (const float*)d_in[10];
    const float* lin1_b      = (const float*)d_in[11];
    const float* lin2_w      = (const float*)d_in[12];
    const float* lin2_b      = (const float*)d_in[13];
    const float* ln_w        = (const float*)d_in[14];
    const float* ln_b        = (const float*)d_in[15];
    const float* fc_out_w    = (const float*)d_in[16];

    float* out    = (float*)d_out;
    float* logits = out;
    float* ft     = out + (long)NDEC * VOC;

    float *px, *po, *pq, *pqkv, *pkv, *pdec;
    __half *hx, *hattn, *hff, *hdec, *hfv;
    __half *hsi, *hso, *hci, *hco, *hl1, *hl2, *hfc;
    cudaGetSymbolAddress((void**)&px,    g_x);
    cudaGetSymbolAddress((void**)&po,    g_o);
    cudaGetSymbolAddress((void**)&pq,    g_q);
    cudaGetSymbolAddress((void**)&pqkv,  g_qkv);
    cudaGetSymbolAddress((void**)&pkv,   g_kv);
    cudaGetSymbolAddress((void**)&pdec,  g_dec);
    cudaGetSymbolAddress((void**)&hx,    g_hx);
    cudaGetSymbolAddress((void**)&hattn, g_hattn);
    cudaGetSymbolAddress((void**)&hff,   g_hff);
    cudaGetSymbolAddress((void**)&hdec,  g_hdec);
    cudaGetSymbolAddress((void**)&hfv,   g_hfv);
    cudaGetSymbolAddress((void**)&hsi,   g_h_si);
    cudaGetSymbolAddress((void**)&hso,   g_h_so);
    cudaGetSymbolAddress((void**)&hci,   g_h_ci);
    cudaGetSymbolAddress((void**)&hco,   g_h_co);
    cudaGetSymbolAddress((void**)&hl1,   g_h_l1);
    cudaGetSymbolAddress((void**)&hl2,   g_h_l2);
    cudaGetSymbolAddress((void**)&hfc,   g_h_fc);

    // weight conversions (per replay; ~100us total)
    f2h_kernel<<<conv_grid((long)NL*3*Dm*Dm), 256>>>(self_in_w,  hsi, NL*3*Dm*Dm);
    f2h_kernel<<<conv_grid((long)NL*Dm*Dm),   256>>>(self_out_w, hso, NL*Dm*Dm);
    f2h_kernel<<<conv_grid((long)NL*3*Dm*Dm), 256>>>(cross_in_w, hci, NL*3*Dm*Dm);
    f2h_kernel<<<conv_grid((long)NL*Dm*Dm),   256>>>(cross_out_w,hco, NL*Dm*Dm);
    f2h_kernel<<<conv_grid((long)NL*FFd*Dm),  256>>>(lin1_w,     hl1, NL*FFd*Dm);
    f2h_kernel<<<conv_grid((long)NL*Dm*FFd),  256>>>(lin2_w,     hl2, NL*Dm*FFd);
    f2h_kernel<<<conv_grid((long)VOC*Dm),     256>>>(fc_out_w,   hfc, (int)((long)VOC*Dm));
    f2h_kernel<<<conv_grid((long)NMEM*Dm),    256>>>(fv,         hfv, NMEM*Dm);

    pe_kernel<<<(NTOK * Dm + 255) / 256, 256>>>(te, px, hx);

    dim3 agrid(Sq / TQ, NHh, Bq);

    for (int l = 0; l < NL; l++) {
        const __half* siw = hsi + (long)l * 3 * Dm * Dm;
        const __half* sow = hso + (long)l * Dm * Dm;
        const __half* ciw = hci + (long)l * 3 * Dm * Dm;
        const __half* cow = hco + (long)l * Dm * Dm;
        const __half* l1w = hl1 + (long)l * FFd * Dm;
        const __half* l2w = hl2 + (long)l * Dm * FFd;
        const float* sib = self_in_b  + (long)l * 3 * Dm;
        const float* sob = self_out_b + (long)l * Dm;
        const float* cib = cross_in_b  + (long)l * 3 * Dm;
        const float* cob = cross_out_b + (long)l * Dm;
        const float* l1b = lin1_b + (long)l * FFd;
        const float* l2b = lin2_b + (long)l * Dm;
        const float* lw  = ln_w + (long)l * 3 * Dm;
        const float* lb  = ln_b + (long)l * 3 * Dm;

        // ---- self attention ----
        mma_gemm<<<gemm_grid(NTOK, 3 * Dm), 256>>>(hx, siw, sib, pqkv, nullptr,
                                                   NTOK, 3 * Dm, Dm, 0);
        attn_tile<<<agrid, 128>>>(pqkv, 3 * Dm,
                                  pqkv + Dm, 3 * Dm,
                                  pqkv + 2 * Dm, 3 * Dm,
                                  hattn, Dm, Sq, 1);
        mma_gemm<<<gemm_grid(NTOK, Dm), 256>>>(hattn, sow, sob, po, nullptr,
                                               NTOK, Dm, Dm, 0);
        add_ln_kernel<<<NTOK, 256>>>(px, po, lw, lb, hx);

        // ---- cross attention ----
        mma_gemm<<<gemm_grid(NTOK, Dm), 256>>>(hx, ciw, cib, pq, nullptr,
                                               NTOK, Dm, Dm, 0);
        mma_gemm<<<gemm_grid(NMEM, 2 * Dm), 256>>>(hfv, ciw + (long)Dm * Dm,
                                                   cib + Dm, pkv, nullptr,
                                                   NMEM, 2 * Dm, Dm, 0);
        attn_tile<<<agrid, 128>>>(pq, Dm,
                                  pkv, 2 * Dm,
                                  pkv + Dm, 2 * Dm,
                                  hattn, Dm, NV, 0);
        mma_gemm<<<gemm_grid(NTOK, Dm), 256>>>(hattn, cow, cob, po, nullptr,
                                               NTOK, Dm, Dm, 0);
        add_ln_kernel<<<NTOK, 256>>>(px, po, lw + Dm, lb + Dm, hx);

        // ---- FFN ----
        mma_gemm<<<gemm_grid(NTOK, FFd), 256>>>(hx, l1w, l1b, nullptr, hff,
                                                NTOK, FFd, Dm, 1);
        mma_gemm<<<gemm_grid(NTOK, Dm), 256>>>(hff, l2w, l2b, po, nullptr,
                                               NTOK, Dm, FFd, 0);
        add_ln_kernel<<<NTOK, 256>>>(px, po, lw + 2 * Dm, lb + 2 * Dm, hx);
    }

    dec_gather<<<(NDEC * Dm + 255) / 256, 256>>>(px, pdec, hdec);
    mma_gemm<<<gemm_grid(NDEC, VOC), 256>>>(hdec, hfc, nullptr, logits, nullptr,
                                            NDEC, VOC, Dm, 0);
    ft_softmax<<<NDEC, 256>>>(pdec, ft);
}

// round 14
// speedup vs baseline: 2.1573x; 2.1573x over previous
#include <cuda_runtime.h>
#include <cuda_fp16.h>
#include <math.h>
#include <stdint.h>

#define Bq   16
#define Sq   256
#define NV   196
#define Dm   768
#define FFd  2048
#define VOC  30522
#define NL   6
#define NHh  8
#define HD   96
#define NTOK (Bq*Sq)        // 4096
#define NMEM (Bq*NV)        // 3136
#define NDEC (Bq*(Sq-1))    // 4080

// -------- scratch (device globals; no allocations allowed) --------
__device__ float  g_x   [NTOK*Dm];
__device__ float  g_o   [NTOK*Dm];
__device__ float  g_dec [NDEC*Dm];
// fp16 activations
__device__ __half g_hx   [NTOK*Dm];
__device__ __half g_hattn[NTOK*Dm];
__device__ __half g_hff  [NTOK*FFd];
__device__ __half g_hdec [NDEC*Dm];
__device__ __half g_hfv  [NMEM*Dm];
__device__ __half g_hqkv [NTOK*3*Dm];
__device__ __half g_hq   [NTOK*Dm];
__device__ __half g_hkv  [NMEM*2*Dm];
// fp16 weights (converted once per launch)
__device__ __half g_h_si[NL*3*Dm*Dm];
__device__ __half g_h_so[NL*Dm*Dm];
__device__ __half g_h_ci[NL*3*Dm*Dm];
__device__ __half g_h_co[NL*Dm*Dm];
__device__ __half g_h_l1[NL*FFd*Dm];
__device__ __half g_h_l2[NL*Dm*FFd];
__device__ __half g_h_fc[(long)VOC*Dm];

// -------- fp32 -> fp16 bulk convert (8 elems/thread) --------
__global__ void f2h_kernel(const float* __restrict__ in, __half* __restrict__ out, int n)
{
    int i = (blockIdx.x * 256 + threadIdx.x) * 8;
    if (i >= n) return;
    float4 v0 = *(const float4*)&in[i];
    float4 v1 = *(const float4*)&in[i + 4];
    uint2 o0, o1;
    __half2 h;
    h = __floats2half2_rn(v0.x, v0.y); o0.x = *(uint32_t*)&h;
    h = __floats2half2_rn(v0.z, v0.w); o0.y = *(uint32_t*)&h;
    h = __floats2half2_rn(v1.x, v1.y); o1.x = *(uint32_t*)&h;
    h = __floats2half2_rn(v1.z, v1.w); o1.y = *(uint32_t*)&h;
    *(uint2*)&out[i]     = o0;
    *(uint2*)&out[i + 4] = o1;
}

// ================== common PTX helpers ==================
__device__ __forceinline__ uint32_t cvta_smem(const void* p) {
    uint32_t a;
    asm("{ .reg .u64 t; cvta.to.shared.u64 t, %1; cvt.u32.u64 %0, t; }"
        : "=r"(a) : "l"(p));
    return a;
}

__device__ __forceinline__ void mma_f16(
    float& c0, float& c1, float& c2, float& c3,
    uint32_t a0, uint32_t a1, uint32_t a2, uint32_t a3,
    uint32_t b0, uint32_t b1)
{
    asm volatile(
        "mma.sync.aligned.m16n8k16.row.col.f32.f16.f16.f32 "
        "{%0,%1,%2,%3}, {%4,%5,%6,%7}, {%8,%9}, {%0,%1,%2,%3};"
        : "+f"(c0), "+f"(c1), "+f"(c2), "+f"(c3)
        : "r"(a0), "r"(a1), "r"(a2), "r"(a3), "r"(b0), "r"(b1));
}

#define LDM_X4(r, addr) \
    asm volatile("ldmatrix.sync.aligned.m8n8.x4.shared.b16 {%0,%1,%2,%3}, [%4];" \
        : "=r"((r)[0]), "=r"((r)[1]), "=r"((r)[2]), "=r"((r)[3]) : "r"(addr))

#define LDM_X4_T(r, addr) \
    asm volatile("ldmatrix.sync.aligned.m8n8.x4.trans.shared.b16 {%0,%1,%2,%3}, [%4];" \
        : "=r"((r)[0]), "=r"((r)[1]), "=r"((r)[2]), "=r"((r)[3]) : "r"(addr))

// ================== FP16 GEMM (R12-proven mainloop) ==================
#define BM 128
#define BN 128
#define BK 16
#define PADW 12

__global__ __launch_bounds__(256, 2) void mma_gemm(
    const __half* __restrict__ A, const __half* __restrict__ W,
    const float* __restrict__ bias,
    float* __restrict__ Cf, __half* __restrict__ Ch,
    int M, int N, int K, int relu)
{
    __shared__ uint32_t As[2][BM * PADW];
    __shared__ uint32_t Bs[2][BN * PADW];

    int tid  = threadIdx.x;
    int wid  = tid >> 5, lane = tid & 31;
    int g    = lane >> 2;
    int t4   = lane & 3;
    int wm   = (wid >> 2) * 64;
    int wn   = (wid & 3) * 32;
    int m0   = blockIdx.y * BM, n0 = blockIdx.x * BN;

    int r = tid >> 1, c = tid & 1;
    int ra = m0 + r; if (ra > M - 1) ra = M - 1;
    int rb = n0 + r; if (rb > N - 1) rb = N - 1;
    const __half* Ap = A + (long)ra * K + c * 8;
    const __half* Wp = W + (long)rb * K + c * 8;
    int sidx = r * PADW + c * 4;

    int rA  = lane & 15, khA = lane >> 4;
    uint32_t aoff = (uint32_t)(((wm + rA) * PADW + khA * 4) * 4);
    int qd = lane >> 3, rB = lane & 7;
    uint32_t boff = (uint32_t)(((wn + ((qd >> 1) * 8) + rB) * PADW + (qd & 1) * 4) * 4);

    uint32_t asb[2] = { cvta_smem(As[0]), cvta_smem(As[1]) };
    uint32_t bsb[2] = { cvta_smem(Bs[0]), cvta_smem(Bs[1]) };

    float acc[4][4][4];
    #pragma unroll
    for (int i = 0; i < 4; i++)
        #pragma unroll
        for (int j = 0; j < 4; j++)
            #pragma unroll
            for (int k = 0; k < 4; k++) acc[i][j][k] = 0.f;

    uint4 ra_v, rb_v;
    ra_v = *(const uint4*)(Ap);
    rb_v = *(const uint4*)(Wp);
    *(uint4*)&As[0][sidx] = ra_v;
    *(uint4*)&Bs[0][sidx] = rb_v;
    __syncthreads();

    int nk = K / BK;
    int buf = 0;
    for (int t = 0; t < nk; t++) {
        if (t + 1 < nk) {
            int ko = (t + 1) * BK;
            ra_v = *(const uint4*)(Ap + ko);
            rb_v = *(const uint4*)(Wp + ko);
        }

        uint32_t af[4][4], bf[4][2];
        #pragma unroll
        for (int mt = 0; mt < 4; mt++)
            LDM_X4(af[mt], asb[buf] + aoff + (uint32_t)(mt * 16 * PADW * 4));
        #pragma unroll
        for (int p = 0; p < 2; p++) {
            uint32_t bb[4];
            LDM_X4(bb, bsb[buf] + boff + (uint32_t)(p * 16 * PADW * 4));
            bf[2*p][0]   = bb[0]; bf[2*p][1]   = bb[1];
            bf[2*p+1][0] = bb[2]; bf[2*p+1][1] = bb[3];
        }
        #pragma unroll
        for (int mt = 0; mt < 4; mt++)
            #pragma unroll
            for (int nt = 0; nt < 4; nt++)
                mma_f16(acc[mt][nt][0], acc[mt][nt][1], acc[mt][nt][2], acc[mt][nt][3],
                        af[mt][0], af[mt][1], af[mt][2], af[mt][3],
                        bf[nt][0], bf[nt][1]);

        if (t + 1 < nk) {
            __syncthreads();
            *(uint4*)&As[buf ^ 1][sidx] = ra_v;
            *(uint4*)&Bs[buf ^ 1][sidx] = rb_v;
            __syncthreads();
            buf ^= 1;
        }
    }

    #pragma unroll
    for (int mt = 0; mt < 4; mt++) {
        int row = m0 + wm + mt * 16 + g;
        #pragma unroll
        for (int nt = 0; nt < 4; nt++) {
            int col = n0 + wn + nt * 8 + t4 * 2;
            float v0 = acc[mt][nt][0], v1 = acc[mt][nt][1];
            float v2 = acc[mt][nt][2], v3 = acc[mt][nt][3];
            if (bias) {
                float b0 = (col < N) ? bias[col] : 0.f;
                float b1 = (col + 1 < N) ? bias[col + 1] : 0.f;
                v0 += b0; v1 += b1; v2 += b0; v3 += b1;
            }
            if (relu) {
                v0 = fmaxf(v0, 0.f); v1 = fmaxf(v1, 0.f);
                v2 = fmaxf(v2, 0.f); v3 = fmaxf(v3, 0.f);
            }
            if (Ch) {
                if (row < M && col + 1 < N)
                    *(__half2*)&Ch[(long)row * N + col] = __floats2half2_rn(v0, v1);
                if (row + 8 < M && col + 1 < N)
                    *(__half2*)&Ch[(long)(row + 8) * N + col] = __floats2half2_rn(v2, v3);
            } else {
                if (row < M) {
                    if (col + 1 < N) *(float2*)&Cf[(long)row * N + col] = make_float2(v0, v1);
                    else if (col < N) Cf[(long)row * N + col] = v0;
                }
                if (row + 8 < M) {
                    if (col + 1 < N) *(float2*)&Cf[(long)(row + 8) * N + col] = make_float2(v2, v3);
                    else if (col < N) Cf[(long)(row + 8) * N + col] = v2;
                }
            }
        }
    }
}

// ================== tensor-core flash attention ==================
// 128 threads, 64 queries per block, one (b,h). fp16 in/out, fp32 softmax.
#define FTQ 64
#define FKC 32
#define LDH 104   // half stride: 208B rows -> conflict-free ldmatrix

__global__ __launch_bounds__(128) void flash_attn(
    const __half* __restrict__ Q, int qs,
    const __half* __restrict__ K, int ks,
    const __half* __restrict__ V, int vs,
    __half* __restrict__ O, int os,
    int Lk, int causal)
{
    __shared__ __half Qs[FTQ][LDH];
    __shared__ __half Ks[FKC][LDH];
    __shared__ __half Vs[FKC][LDH];

    int tid  = threadIdx.x;
    int warp = tid >> 5, lane = tid & 31;
    int g = lane >> 2, t4 = lane & 3;
    int q0 = blockIdx.x * FTQ;
    int h  = blockIdx.y, b = blockIdx.z;

    const __half* Qb = Q + ((long)b * Sq + q0) * qs + h * HD;
    const __half* Kb = K + (long)b * Lk * ks + h * HD;
    const __half* Vb = V + (long)b * Lk * vs + h * HD;

    #pragma unroll
    for (int i = 0; i < 6; i++) {
        int idx = tid + i * 128;
        int row = idx / 12, col = (idx % 12) * 8;
        *(uint4*)&Qs[row][col] = *(const uint4*)&Qb[(long)row * qs + col];
    }
    __syncthreads();

    // Q fragments (held for the whole kernel)
    uint32_t qf[6][4];
    {
        uint32_t qbase = cvta_smem(Qs);
        int row = 16 * warp + (lane & 15);
        int colh = (lane >> 4) * 8;
        #pragma unroll
        for (int kk = 0; kk < 6; kk++)
            LDM_X4(qf[kk], qbase + (uint32_t)((row * LDH + colh + kk * 16) * 2));
    }

    float o[12][4];
    #pragma unroll
    for (int i = 0; i < 12; i++)
        #pragma unroll
        for (int j = 0; j < 4; j++) o[i][j] = 0.f;
    float m0 = -1e30f, m1 = -1e30f, l0 = 0.f, l1 = 0.f;

    uint32_t kbase = cvta_smem(Ks), vbase = cvta_smem(Vs);
    int qd = lane >> 3, rB = lane & 7;
    int vrow_off = ((lane >> 3) & 1) * 8 + (lane & 7);
    int vcol_off = (lane >> 4) * 8;
    const float scale = rsqrtf((float)HD);
    int qrow0 = q0 + 16 * warp + g, qrow1 = qrow0 + 8;

    int nch = (Lk + FKC - 1) / FKC;
    for (int ch = 0; ch < nch; ch++) {
        int k0 = ch * FKC;
        if (causal && k0 > q0 + FTQ - 1) break;
        __syncthreads();
        #pragma unroll
        for (int i = 0; i < 3; i++) {
            int idx = tid + i * 128;
            int row = idx / 12, col = (idx % 12) * 8;
            int kr = k0 + row;
            if (kr < Lk) {
                *(uint4*)&Ks[row][col] = *(const uint4*)&Kb[(long)kr * ks + col];
                *(uint4*)&Vs[row][col] = *(const uint4*)&Vb[(long)kr * vs + col];
            } else {
                uint4 z = make_uint4(0u, 0u, 0u, 0u);
                *(uint4*)&Ks[row][col] = z;
                *(uint4*)&Vs[row][col] = z;
            }
        }
        __syncthreads();

        // ---- S = Q @ K^T (4 key-tiles of 8) ----
        float s[4][4];
        #pragma unroll
        for (int j = 0; j < 4; j++)
            #pragma unroll
            for (int cc = 0; cc < 4; cc++) s[j][cc] = 0.f;
        #pragma unroll
        for (int kk = 0; kk < 6; kk++) {
            #pragma unroll
            for (int p = 0; p < 2; p++) {
                uint32_t bb[4];
                int krow = 16 * p + (qd >> 1) * 8 + rB;
                LDM_X4(bb, kbase + (uint32_t)((krow * LDH + (qd & 1) * 8 + kk * 16) * 2));
                mma_f16(s[2*p][0], s[2*p][1], s[2*p][2], s[2*p][3],
                        qf[kk][0], qf[kk][1], qf[kk][2], qf[kk][3], bb[0], bb[1]);
                mma_f16(s[2*p+1][0], s[2*p+1][1], s[2*p+1][2], s[2*p+1][3],
                        qf[kk][0], qf[kk][1], qf[kk][2], qf[kk][3], bb[2], bb[3]);
            }
        }
        // ---- scale + mask ----
        #pragma unroll
        for (int j = 0; j < 4; j++) {
            int c0 = k0 + 8 * j + 2 * t4, c1 = c0 + 1;
            s[j][0] = (c0 < Lk && (!causal || c0 <= qrow0)) ? s[j][0] * scale : -1e30f;
            s[j][1] = (c1 < Lk && (!causal || c1 <= qrow0)) ? s[j][1] * scale : -1e30f;
            s[j][2] = (c0 < Lk && (!causal || c0 <= qrow1)) ? s[j][2] * scale : -1e30f;
            s[j][3] = (c1 < Lk && (!causal || c1 <= qrow1)) ? s[j][3] * scale : -1e30f;
        }
        // ---- online softmax ----
        float rm0 = -1e30f, rm1 = -1e30f;
        #pragma unroll
        for (int j = 0; j < 4; j++) {
            rm0 = fmaxf(rm0, fmaxf(s[j][0], s[j][1]));
            rm1 = fmaxf(rm1, fmaxf(s[j][2], s[j][3]));
        }
        rm0 = fmaxf(rm0, __shfl_xor_sync(~0u, rm0, 1));
        rm0 = fmaxf(rm0, __shfl_xor_sync(~0u, rm0, 2));
        rm1 = fmaxf(rm1, __shfl_xor_sync(~0u, rm1, 1));
        rm1 = fmaxf(rm1, __shfl_xor_sync(~0u, rm1, 2));
        float mn0 = fmaxf(m0, rm0), mn1 = fmaxf(m1, rm1);
        float f0 = __expf(m0 - mn0), f1 = __expf(m1 - mn1);
        m0 = mn0; m1 = mn1;
        float sum0 = 0.f, sum1 = 0.f;
        uint32_t pa[2][4];
        #pragma unroll
        for (int j = 0; j < 4; j++) {
            float p00 = __expf(s[j][0] - mn0);
            float p01 = __expf(s[j][1] - mn0);
            float p10 = __expf(s[j][2] - mn1);
            float p11 = __expf(s[j][3] - mn1);
            sum0 += p00 + p01; sum1 += p10 + p11;
            __half2 hh = __floats2half2_rn(p00, p01);
            pa[j >> 1][(j & 1) * 2 + 0] = *(uint32_t*)&hh;
            hh = __floats2half2_rn(p10, p11);
            pa[j >> 1][(j & 1) * 2 + 1] = *(uint32_t*)&hh;
        }
        l0 = l0 * f0 + sum0;
        l1 = l1 * f1 + sum1;
        #pragma unroll
        for (int nt = 0; nt < 12; nt++) {
            o[nt][0] *= f0; o[nt][1] *= f0;
            o[nt][2] *= f1; o[nt][3] *= f1;
        }
        // ---- O += P @ V ----
        #pragma unroll
        for (int st = 0; st < 2; st++) {
            #pragma unroll
            for (int np = 0; np < 6; np++) {
                uint32_t bb[4];
                int krow = st * 16 + vrow_off;
                int ncol = np * 16 + vcol_off;
                LDM_X4_T(bb, vbase + (uint32_t)((krow * LDH + ncol) * 2));
                mma_f16(o[2*np][0], o[2*np][1], o[2*np][2], o[2*np][3],
                        pa[st][0], pa[st][1], pa[st][2], pa[st][3], bb[0], bb[1]);
                mma_f16(o[2*np+1][0], o[2*np+1][1], o[2*np+1][2], o[2*np+1][3],
                        pa[st][0], pa[st][1], pa[st][2], pa[st][3], bb[2], bb[3]);
            }
        }
    }

    // ---- finalize ----
    l0 += __shfl_xor_sync(~0u, l0, 1);
    l0 += __shfl_xor_sync(~0u, l0, 2);
    l1 += __shfl_xor_sync(~0u, l1, 1);
    l1 += __shfl_xor_sync(~0u, l1, 2);
    float inv0 = 1.f / l0, inv1 = 1.f / l1;
    __half* Ob = O + ((long)b * Sq + q0 + 16 * warp) * os + h * HD;
    #pragma unroll
    for (int nt = 0; nt < 12; nt++) {
        int col = 8 * nt + 2 * t4;
        *(__half2*)&Ob[(long)g * os + col] =
            __floats2half2_rn(o[nt][0] * inv0, o[nt][1] * inv0);
        *(__half2*)&Ob[(long)(g + 8) * os + col] =
            __floats2half2_rn(o[nt][2] * inv1, o[nt][3] * inv1);
    }
}

// -------- residual add + layernorm (in-place on X, dual write fp16) ------
__global__ __launch_bounds__(256) void add_ln_kernel(
    float* __restrict__ X, const float* __restrict__ Y,
    const float* __restrict__ w, const float* __restrict__ b,
    __half* __restrict__ HX)
{
    long t = blockIdx.x;
    int tid = threadIdx.x;
    __shared__ float red[256];
    float vals[3];
    float s = 0.f;
    #pragma unroll
    for (int i = 0; i < 3; i++) {
        int d = tid + i * 256;
        float v = X[t * Dm + d] + Y[t * Dm + d];
        vals[i] = v;
        s += v;
    }
    red[tid] = s; __syncthreads();
    for (int st = 128; st > 0; st >>= 1) {
        if (tid < st) red[tid] += red[tid + st];
        __syncthreads();
    }
    float mean = red[0] * (1.f / Dm);
    __syncthreads();
    float s2 = 0.f;
    #pragma unroll
    for (int i = 0; i < 3; i++) { float dv = vals[i] - mean; s2 += dv * dv; }
    red[tid] = s2; __syncthreads();
    for (int st = 128; st > 0; st >>= 1) {
        if (tid < st) red[tid] += red[tid + st];
        __syncthreads();
    }
    float rstd = rsqrtf(red[0] * (1.f / Dm) + 1e-5f);
    #pragma unroll
    for (int i = 0; i < 3; i++) {
        int d = tid + i * 256;
        float o = (vals[i] - mean) * rstd * w[d] + b[d];
        X[t * Dm + d]  = o;
        HX[t * Dm + d] = __float2half_rn(o);
    }
}

// -------- x = target_embed + sinusoid PE (dual write) --------
__global__ void pe_kernel(const float* __restrict__ te,
                          float* __restrict__ x, __half* __restrict__ hx)
{
    int idx = blockIdx.x * 256 + threadIdx.x;
    if (idx >= NTOK * Dm) return;
    int d = idx % Dm;
    int tok = idx / Dm;
    int s = tok % Sq;
    int j = d >> 1;
    float div = expf(-(float)(2 * j) * (logf(10000.f) / (float)Dm));
    float ang = (float)s * div;
    float p = (d & 1) ? cosf(ang) : sinf(ang);
    float o = te[idx] + p;
    x[idx]  = o;
    hx[idx] = __float2half_rn(o);
}

// -------- gather dec = x[:, :S-1, :] (dual write) --------
__global__ void dec_gather(const float* __restrict__ x,
                           float* __restrict__ dec, __half* __restrict__ hdec)
{
    int idx = blockIdx.x * 256 + threadIdx.x;
    if (idx >= NDEC * Dm) return;
    int d = idx % Dm;
    int rr = idx / Dm;
    int b = rr / (Sq - 1);
    int s = rr % (Sq - 1);
    float v = x[((long)(b * Sq + s)) * Dm + d];
    dec[idx]  = v;
    hdec[idx] = __float2half_rn(v);
}

// -------- F_t = softmax(dec, axis=-1) --------
__global__ __launch_bounds__(256) void ft_softmax(
    const float* __restrict__ dec, float* __restrict__ out)
{
    long rr = blockIdx.x;
    int tid = threadIdx.x;
    __shared__ float red[256];
    float v[3];
    float mx = -1e30f;
    #pragma unroll
    for (int i = 0; i < 3; i++) {
        v[i] = dec[rr * Dm + tid + i * 256];
        mx = fmaxf(mx, v[i]);
    }
    red[tid] = mx; __syncthreads();
    for (int st = 128; st > 0; st >>= 1) {
        if (tid < st) red[tid] = fmaxf(red[tid], red[tid + st]);
        __syncthreads();
    }
    float m = red[0]; __syncthreads();
    float s = 0.f;
    #pragma unroll
    for (int i = 0; i < 3; i++) { v[i] = __expf(v[i] - m); s += v[i]; }
    red[tid] = s; __syncthreads();
    for (int st = 128; st > 0; st >>= 1) {
        if (tid < st) red[tid] += red[tid + st];
        __syncthreads();
    }
    float inv = 1.f / red[0];
    #pragma unroll
    for (int i = 0; i < 3; i++)
        out[rr * Dm + tid + i * 256] = v[i] * inv;
}

static inline dim3 gemm_grid(int M, int N) {
    return dim3((N + BN - 1) / BN, (M + BM - 1) / BM);
}
static inline int conv_grid(long n) { return (int)((n / 8 + 255) / 256); }

extern "C" void kernel_launch(void* const* d_in, const int* in_sizes, int n_in,
                              void* d_out, int out_size)
{
    const float* fv          = (const float*)d_in[0];
    const float* te          = (const float*)d_in[1];
    const float* self_in_w   = (const float*)d_in[2];
    const float* self_in_b   = (const float*)d_in[3];
    const float* self_out_w  = (const float*)d_in[4];
    const float* self_out_b  = (const float*)d_in[5];
    const float* cross_in_w  = (const float*)d_in[6];
    const float* cross_in_b  = (const float*)d_in[7];
    const float* cross_out_w = (const float*)d_in[8];
    const float* cross_out_b = (const float*)d_in[9];
    const float* lin1_w      = (const float*)d_in[10];
    const float* lin1_b      = (const float*)d_in[11];
    const float* lin2_w      = (const float*)d_in[12];
    const float* lin2_b      = (const float*)d_in[13];
    const float* ln_w        = (const float*)d_in[14];
    const float* ln_b        = (const float*)d_in[15];
    const float* fc_out_w    = (const float*)d_in[16];

    float* out    = (float*)d_out;
    float* logits = out;
    float* ft     = out + (long)NDEC * VOC;

    float *px, *po, *pdec;
    __half *hx, *hattn, *hff, *hdec, *hfv, *hqkv, *hq, *hkv;
    __half *hsi, *hso, *hci, *hco, *hl1, *hl2, *hfc;
    cudaGetSymbolAddress((void**)&px,    g_x);
    cudaGetSymbolAddress((void**)&po,    g_o);
    cudaGetSymbolAddress((void**)&pdec,  g_dec);
    cudaGetSymbolAddress((void**)&hx,    g_hx);
    cudaGetSymbolAddress((void**)&hattn, g_hattn);
    cudaGetSymbolAddress((void**)&hff,   g_hff);
    cudaGetSymbolAddress((void**)&hdec,  g_hdec);
    cudaGetSymbolAddress((void**)&hfv,   g_hfv);
    cudaGetSymbolAddress((void**)&hqkv,  g_hqkv);
    cudaGetSymbolAddress((void**)&hq,    g_hq);
    cudaGetSymbolAddress((void**)&hkv,   g_hkv);
    cudaGetSymbolAddress((void**)&hsi,   g_h_si);
    cudaGetSymbolAddress((void**)&hso,   g_h_so);
    cudaGetSymbolAddress((void**)&hci,   g_h_ci);
    cudaGetSymbolAddress((void**)&hco,   g_h_co);
    cudaGetSymbolAddress((void**)&hl1,   g_h_l1);
    cudaGetSymbolAddress((void**)&hl2,   g_h_l2);
    cudaGetSymbolAddress((void**)&hfc,   g_h_fc);

    f2h_kernel<<<conv_grid((long)NL*3*Dm*Dm), 256>>>(self_in_w,  hsi, NL*3*Dm*Dm);
    f2h_kernel<<<conv_grid((long)NL*Dm*Dm),   256>>>(self_out_w, hso, NL*Dm*Dm);
    f2h_kernel<<<conv_grid((long)NL*3*Dm*Dm), 256>>>(cross_in_w, hci, NL*3*Dm*Dm);
    f2h_kernel<<<conv_grid((long)NL*Dm*Dm),   256>>>(cross_out_w,hco, NL*Dm*Dm);
    f2h_kernel<<<conv_grid((long)NL*FFd*Dm),  256>>>(lin1_w,     hl1, NL*FFd*Dm);
    f2h_kernel<<<conv_grid((long)NL*Dm*FFd),  256>>>(lin2_w,     hl2, NL*Dm*FFd);
    f2h_kernel<<<conv_grid((long)VOC*Dm),     256>>>(fc_out_w,   hfc, (int)((long)VOC*Dm));
    f2h_kernel<<<conv_grid((long)NMEM*Dm),    256>>>(fv,         hfv, NMEM*Dm);

    pe_kernel<<<(NTOK * Dm + 255) / 256, 256>>>(te, px, hx);

    dim3 agrid(Sq / FTQ, NHh, Bq);

    for (int l = 0; l < NL; l++) {
        const __half* siw = hsi + (long)l * 3 * Dm * Dm;
        const __half* sow = hso + (long)l * Dm * Dm;
        const __half* ciw = hci + (long)l * 3 * Dm * Dm;
        const __half* cow = hco + (long)l * Dm * Dm;
        const __half* l1w = hl1 + (long)l * FFd * Dm;
        const __half* l2w = hl2 + (long)l * Dm * FFd;
        const float* sib = self_in_b  + (long)l * 3 * Dm;
        const float* sob = self_out_b + (long)l * Dm;
        const float* cib = cross_in_b  + (long)l * 3 * Dm;
        const float* cob = cross_out_b + (long)l * Dm;
        const float* l1b = lin1_b + (long)l * FFd;
        const float* l2b = lin2_b + (long)l * Dm;
        const float* lw  = ln_w + (long)l * 3 * Dm;
        const float* lb  = ln_b + (long)l * 3 * Dm;

        // ---- self attention ----
        mma_gemm<<<gemm_grid(NTOK, 3 * Dm), 256>>>(hx, siw, sib, nullptr, hqkv,
                                                   NTOK, 3 * Dm, Dm, 0);
        flash_attn<<<agrid, 128>>>(hqkv, 3 * Dm,
                                   hqkv + Dm, 3 * Dm,
                                   hqkv + 2 * Dm, 3 * Dm,
                                   hattn, Dm, Sq, 1);
        mma_gemm<<<gemm_grid(NTOK, Dm), 256>>>(hattn, sow, sob, po, nullptr,
                                               NTOK, Dm, Dm, 0);
        add_ln_kernel<<<NTOK, 256>>>(px, po, lw, lb, hx);

        // ---- cross attention ----
        mma_gemm<<<gemm_grid(NTOK, Dm), 256>>>(hx, ciw, cib, nullptr, hq,
                                               NTOK, Dm, Dm, 0);
        mma_gemm<<<gemm_grid(NMEM, 2 * Dm), 256>>>(hfv, ciw + (long)Dm * Dm,
                                                   cib + Dm, nullptr, hkv,
                                                   NMEM, 2 * Dm, Dm, 0);
        flash_attn<<<agrid, 128>>>(hq, Dm,
                                   hkv, 2 * Dm,
                                   hkv + Dm, 2 * Dm,
                                   hattn, Dm, NV, 0);
        mma_gemm<<<gemm_grid(NTOK, Dm), 256>>>(hattn, cow, cob, po, nullptr,
                                               NTOK, Dm, Dm, 0);
        add_ln_kernel<<<NTOK, 256>>>(px, po, lw + Dm, lb + Dm, hx);

        // ---- FFN ----
        mma_gemm<<<gemm_grid(NTOK, FFd), 256>>>(hx, l1w, l1b, nullptr, hff,
                                                NTOK, FFd, Dm, 1);
        mma_gemm<<<gemm_grid(NTOK, Dm), 256>>>(hff, l2w, l2b, po, nullptr,
                                               NTOK, Dm, FFd, 0);
        add_ln_kernel<<<NTOK, 256>>>(px, po, lw + 2 * Dm, lb + 2 * Dm, hx);
    }

    dec_gather<<<(NDEC * Dm + 255) / 256, 256>>>(px, pdec, hdec);
    mma_gemm<<<gemm_grid(NDEC, VOC), 256>>>(hdec, hfc, nullptr, logits, nullptr,
                                            NDEC, VOC, Dm, 0);
    ft_softmax<<<NDEC, 256>>>(pdec, ft);
}